// round 9
// baseline (speedup 1.0000x reference)
#include <cuda_runtime.h>
#include <math.h>

#define BB   8
#define CC   64
#define CR   8
#define HH   64
#define WWD  64
#define NPIX 4096   // HH*WWD
#define NBLK 128    // persistent grid: <= SM count (148); 128 = BB*16 chunks
#define NTHR 1024

// ---------------- device scratch (static, no allocation) ----------------
// per-(b,chunk) per-channel partials; fully rewritten each launch (graph-safe)
__device__ float d_part_sum[BB * 16 * CC];
__device__ float d_part_max[BB * 16 * CC];
__device__ float d_sa_avg[BB * NPIX];
__device__ float d_sa_max[BB * NPIX];
// PAM fallback scratch (only written when gamma != 0)
__device__ float d_q[BB * CR * NPIX];
__device__ float d_k[BB * CR * NPIX];
__device__ float d_v[BB * CC * NPIX];
__device__ __align__(16) float d_pam[BB * CC * NPIX];
// grid barrier ticket counter (monotonic; safe across graph replays)
__device__ unsigned long long g_bar;

__device__ __forceinline__ void grid_barrier() {
    __syncthreads();
    if (threadIdx.x == 0) {
        __threadfence();
        const unsigned long long t = atomicAdd(&g_bar, 1ULL);
        const unsigned long long release = (t / NBLK + 1ULL) * (unsigned long long)NBLK;
        volatile unsigned long long* p = &g_bar;
        while (*p < release) { }
    }
    __syncthreads();
}

__global__ void __launch_bounds__(NTHR, 1)
k_pcbam(const float* __restrict__ x,
        const float* __restrict__ fc1,   // [CR, C]
        const float* __restrict__ fc2,   // [C, CR]
        const float* __restrict__ qw, const float* __restrict__ qbias,
        const float* __restrict__ kw, const float* __restrict__ kbias,
        const float* __restrict__ vw, const float* __restrict__ vbias,
        const float* __restrict__ gamma,
        const float* __restrict__ sw,    // [2,7,7]
        float* __restrict__ out) {
    const int blk = blockIdx.x;   // 0..127
    const int t   = threadIdx.x;  // 0..1023
    const int b     = blk >> 4;   // batch
    const int chunk = blk & 15;   // 4-row chunk
    const int n0    = chunk << 8;
    const int h0    = chunk << 2;

    // dynamic smem 96 KB:
    //   [0 .. 64KB)   sx[c][256]  : x stash for this block's 4-row tile
    //   [64 .. 80KB)  ps_a[c][64] : per-(channel,px4) partial sums
    //   [80 .. 96KB)  pm_a[c][64] : per-(channel,px4) partial maxes
    // PAM fallback overlays att[NPIX]+red[NTHR] on the first 20KB (g!=0 only).
    extern __shared__ __align__(16) float dyn[];
    float* sx   = dyn;                      // [CC * 256]
    float* ps_a = dyn + CC * 256;           // [CC * 64]
    float* pm_a = dyn + CC * 256 + CC * 64; // [CC * 64]
    float* att  = dyn;                      // fallback only
    float* red  = dyn + NPIX;               // fallback only

    __shared__ float s_sum[CC], s_max[CC];
    __shared__ float ca[CC], h_avg[CR], h_mx[CR];
    __shared__ float ps[4][256], pm[4][256];
    __shared__ float tile_avg[10][70], tile_max[10][70];
    __shared__ float wgt[98];
    __shared__ __align__(16) float mask_s[256];

    const float g = gamma[0];

    // ============ Phase A': single read of x tile + per-channel partials =====
    {
        const int px4 = t & 63;   // float4 index within 256-px chunk
        const int c0  = t >> 6;   // 0..15
        const float4* xb4 = reinterpret_cast<const float4*>(x)
                          + (size_t)b * CC * (NPIX / 4) + (n0 >> 2) + px4;
        #pragma unroll
        for (int k = 0; k < 4; k++) {
            const int c = c0 + 16 * k;
            const float4 v = xb4[(size_t)c * (NPIX / 4)];
            reinterpret_cast<float4*>(&sx[c * 256])[px4] = v;
            ps_a[c * 64 + px4] = (v.x + v.y) + (v.z + v.w);
            pm_a[c * 64 + px4] = fmaxf(fmaxf(v.x, v.y), fmaxf(v.z, v.w));
        }
    }
    __syncthreads();
    {
        const int c = t >> 4, j = t & 15;
        const float4 sv = reinterpret_cast<const float4*>(&ps_a[c * 64])[j];
        const float4 mv = reinterpret_cast<const float4*>(&pm_a[c * 64])[j];
        float s = (sv.x + sv.y) + (sv.z + sv.w);
        float m = fmaxf(fmaxf(mv.x, mv.y), fmaxf(mv.z, mv.w));
        #pragma unroll
        for (int off = 8; off; off >>= 1) {
            s += __shfl_down_sync(0xffffffffu, s, off, 16);
            m  = fmaxf(m, __shfl_down_sync(0xffffffffu, m, off, 16));
        }
        if (j == 0) {
            d_part_sum[(b * 16 + chunk) * CC + c] = s;
            d_part_max[(b * 16 + chunk) * CC + c] = m;
        }
    }

    grid_barrier();

    // ============ Phase B: channel totals + MLP + spatial stats ==============
    {
        const int c = t >> 4, j = t & 15;
        float s = __ldcg(&d_part_sum[(b * 16 + j) * CC + c]);
        float m = __ldcg(&d_part_max[(b * 16 + j) * CC + c]);
        #pragma unroll
        for (int off = 8; off; off >>= 1) {
            s += __shfl_down_sync(0xffffffffu, s, off, 16);
            m  = fmaxf(m, __shfl_down_sync(0xffffffffu, m, off, 16));
        }
        if (j == 0) { s_sum[c] = s * (1.0f / NPIX); s_max[c] = m; }
    }
    __syncthreads();
    if (t < CR) {
        float ha = 0.0f, hm = 0.0f;
        #pragma unroll
        for (int c = 0; c < CC; c++) {
            const float w = fc1[t * CC + c];
            ha += s_sum[c] * w;
            hm += s_max[c] * w;
        }
        h_avg[t] = fmaxf(ha, 0.0f);
        h_mx[t]  = fmaxf(hm, 0.0f);
    }
    __syncthreads();
    if (t < CC) {
        float o = 0.0f;
        #pragma unroll
        for (int r = 0; r < CR; r++)
            o += (h_avg[r] + h_mx[r]) * fc2[t * CR + r];
        ca[t] = 1.0f / (1.0f + expf(-o));
    }
    __syncthreads();
    {
        const int px  = t & 255;
        const int grp = t >> 8;     // 16 channels each
        float s = 0.0f, m = -INFINITY;
        if (g == 0.0f) {
            #pragma unroll
            for (int cc = 0; cc < 16; cc++) {
                const int c = grp * 16 + cc;
                const float v = sx[c * 256 + px] * ca[c];
                s += v;
                m = fmaxf(m, v);
            }
        } else {   // fallback path: stash will be clobbered; use global x
            const float* xb = x + (size_t)b * CC * NPIX + n0 + px;
            #pragma unroll
            for (int cc = 0; cc < 16; cc++) {
                const int c = grp * 16 + cc;
                const float v = xb[c * NPIX] * ca[c];
                s += v;
                m = fmaxf(m, v);
            }
        }
        ps[grp][px] = s;
        pm[grp][px] = m;
        __syncthreads();
        if (t < 256) {
            const float ts = ps[0][t] + ps[1][t] + ps[2][t] + ps[3][t];
            const float tm = fmaxf(fmaxf(pm[0][t], pm[1][t]), fmaxf(pm[2][t], pm[3][t]));
            d_sa_avg[b * NPIX + n0 + t] = ts * (1.0f / CC);
            d_sa_max[b * NPIX + n0 + t] = tm;
        }
    }

    grid_barrier();

    // ============ PAM fallback (uniform branch; benchmark: g==0) =============
    if (g != 0.0f) {
        for (int bn = blk * NTHR + t; bn < BB * NPIX; bn += NBLK * NTHR) {
            const int bb = bn >> 12, n = bn & (NPIX - 1);
            const float* xb = x + (size_t)bb * CC * NPIX + n;
            float qa[CR], ka[CR];
            #pragma unroll
            for (int r = 0; r < CR; r++) { qa[r] = qbias[r]; ka[r] = kbias[r]; }
            for (int c = 0; c < CC; c++) {
                const float xv = xb[c * NPIX];
                #pragma unroll
                for (int r = 0; r < CR; r++) {
                    qa[r] += xv * qw[r * CC + c];
                    ka[r] += xv * kw[r * CC + c];
                }
            }
            #pragma unroll
            for (int r = 0; r < CR; r++) {
                d_q[(bb * CR + r) * NPIX + n] = qa[r];
                d_k[(bb * CR + r) * NPIX + n] = ka[r];
            }
        }
        for (int bcn = blk * NTHR + t; bcn < BB * CC * NPIX; bcn += NBLK * NTHR) {
            const int bc = bcn >> 12;
            const int bb = bc >> 6, c = bc & 63, n = bcn & (NPIX - 1);
            const float* xb = x + (size_t)bb * CC * NPIX + n;
            float acc = vbias[c];
            for (int cc = 0; cc < CC; cc++) acc += xb[cc * NPIX] * vw[c * CC + cc];
            d_v[bcn] = acc;
        }
        grid_barrier();
        for (int row = blk; row < BB * NPIX; row += NBLK) {
            const int bb = row >> 12;
            const int i  = row & (NPIX - 1);
            float qr[CR];
            #pragma unroll
            for (int r = 0; r < CR; r++) qr[r] = __ldcg(&d_q[(bb * CR + r) * NPIX + i]);
            float mx = -INFINITY;
            for (int j = t; j < NPIX; j += NTHR) {
                float e = 0.0f;
                #pragma unroll
                for (int r = 0; r < CR; r++) e += qr[r] * __ldcg(&d_k[(bb * CR + r) * NPIX + j]);
                att[j] = e;
                mx = fmaxf(mx, e);
            }
            red[t] = mx; __syncthreads();
            for (int s = NTHR / 2; s; s >>= 1) {
                if (t < s) red[t] = fmaxf(red[t], red[t + s]);
                __syncthreads();
            }
            mx = red[0]; __syncthreads();
            float sum = 0.0f;
            for (int j = t; j < NPIX; j += NTHR) {
                const float e = expf(att[j] - mx);
                att[j] = e;
                sum += e;
            }
            red[t] = sum; __syncthreads();
            for (int s = NTHR / 2; s; s >>= 1) {
                if (t < s) red[t] += red[t + s];
                __syncthreads();
            }
            const float inv = 1.0f / red[0]; __syncthreads();
            for (int c = 0; c < CC; c++) {
                float acc = 0.0f;
                for (int j = t; j < NPIX; j += NTHR)
                    acc += att[j] * __ldcg(&d_v[(bb * CC + c) * NPIX + j]);
                red[t] = acc; __syncthreads();
                for (int s = NTHR / 2; s; s >>= 1) {
                    if (t < s) red[t] += red[t + s];
                    __syncthreads();
                }
                if (t == 0) d_pam[(bb * CC + c) * NPIX + i] = red[0] * inv;
                __syncthreads();
            }
        }
        grid_barrier();
    }

    // ============ Phase C: halo + 7x7 conv + sigmoid + final combine =========
    for (int i = t; i < 700; i += NTHR) {
        const int r = i / 70, cidx = i % 70;
        const int gh = h0 - 3 + r, gw = cidx - 3;
        float a = 0.0f, mv = 0.0f;
        if ((unsigned)gh < (unsigned)HH && (unsigned)gw < (unsigned)WWD) {
            const int gi = b * NPIX + gh * WWD + gw;
            a  = __ldcg(&d_sa_avg[gi]);
            mv = __ldcg(&d_sa_max[gi]);
        }
        tile_avg[r][cidx] = a;
        tile_max[r][cidx] = mv;
    }
    if (t < 98) wgt[t] = sw[t];
    __syncthreads();
    if (t < 256) {
        const int h = t >> 6, w = t & 63;
        float acc = 0.0f;
        #pragma unroll
        for (int kh = 0; kh < 7; kh++)
            #pragma unroll
            for (int kw2 = 0; kw2 < 7; kw2++)
                acc += tile_avg[h + kh][w + kw2] * wgt[kh * 7 + kw2]
                     + tile_max[h + kh][w + kw2] * wgt[49 + kh * 7 + kw2];
        mask_s[t] = 1.0f / (1.0f + expf(-acc));
    }
    __syncthreads();
    {
        const int px4 = t & 63;
        const int c0  = t >> 6;     // 0..15
        const float4 m4 = reinterpret_cast<const float4*>(mask_s)[px4];
        const size_t base4 = (size_t)b * CC * (NPIX / 4) + (size_t)(n0 >> 2) + px4;
        if (g == 0.0f) {
            #pragma unroll
            for (int k = 0; k < 4; k++) {
                const int c = c0 + 16 * k;
                const float4 xv = reinterpret_cast<const float4*>(&sx[c * 256])[px4];
                const float cav = ca[c];
                float4 o;
                o.x = xv.x * (1.0f + cav * m4.x);
                o.y = xv.y * (1.0f + cav * m4.y);
                o.z = xv.z * (1.0f + cav * m4.z);
                o.w = xv.w * (1.0f + cav * m4.w);
                reinterpret_cast<float4*>(out)[base4 + (size_t)c * (NPIX / 4)] = o;
            }
        } else {
            #pragma unroll
            for (int k = 0; k < 4; k++) {
                const int c = c0 + 16 * k;
                const size_t idx4 = base4 + (size_t)c * (NPIX / 4);
                const float4 xv = reinterpret_cast<const float4*>(x)[idx4];
                const float4 pv = reinterpret_cast<const float4*>(d_pam)[idx4];
                const float cav = ca[c];
                float4 o;
                o.x = xv.x * (1.0f + cav * m4.x) + g * pv.x;
                o.y = xv.y * (1.0f + cav * m4.y) + g * pv.y;
                o.z = xv.z * (1.0f + cav * m4.z) + g * pv.z;
                o.w = xv.w * (1.0f + cav * m4.w) + g * pv.w;
                reinterpret_cast<float4*>(out)[idx4] = o;
            }
        }
    }
}

// ---------------- launch ----------------
extern "C" void kernel_launch(void* const* d_in, const int* in_sizes, int n_in,
                              void* d_out, int out_size) {
    const float* x     = (const float*)d_in[0];
    const float* fc1_w = (const float*)d_in[1];
    const float* fc2_w = (const float*)d_in[2];
    const float* q_w   = (const float*)d_in[3];
    const float* q_b   = (const float*)d_in[4];
    const float* k_w   = (const float*)d_in[5];
    const float* k_b   = (const float*)d_in[6];
    const float* v_w   = (const float*)d_in[7];
    const float* v_b   = (const float*)d_in[8];
    const float* gamma = (const float*)d_in[9];
    const float* sa_w  = (const float*)d_in[10];
    float* out = (float*)d_out;

    const int dyn_bytes = (CC * 256 + CC * 64 * 2) * (int)sizeof(float);   // 96 KB
    cudaFuncSetAttribute(k_pcbam, cudaFuncAttributeMaxDynamicSharedMemorySize, dyn_bytes);
    k_pcbam<<<NBLK, NTHR, dyn_bytes>>>(x, fc1_w, fc2_w, q_w, q_b, k_w, k_b,
                                       v_w, v_b, gamma, sa_w, out);
}